// round 8
// baseline (speedup 1.0000x reference)
#include <cuda_runtime.h>

// DeepKoopman: B=1024,S=512,D=32,L=64,H=64,P=256
// Outputs: x_rec[B,S,D], x_dyn[B,S,D], x_pred[B,P,D], z[B,S,L], z_dyn[B,S,L]

namespace {
constexpr int Bn = 1024, Sn = 512, Dn = 32, Ln = 64, Pn = 256;
constexpr int BS = Bn * Sn;
constexpr long OFF_XREC  = 0;
constexpr long OFF_XDYN  = (long)BS * Dn;
constexpr long OFF_XPRED = OFF_XDYN * 2;
constexpr long OFF_Z     = OFF_XPRED + (long)Bn * Pn * Dn;
constexpr long OFF_ZDYN  = OFF_Z + (long)BS * Ln;
}

// scratch (device globals; no allocation allowed)
__device__ float g_Mpow[256][4096];               // K^p row-major
__device__ float g_MpowT[256][4096];              // transposed
__device__ float g_zlastT[Ln * Bn];               // [L,B]
__device__ float g_ew1T[32 * 64];                 // [i][j]
__device__ float g_ew2T[64 * 64];                 // [j][l]
__device__ float g_KW2T[64 * 64];                 // [j][l'] of (K@W2)
__device__ float g_Kb2[64];                       // K@b2
__device__ float g_dw1T[64 * 64];                 // [l][j]
__device__ float g_dw2T[64 * 32];                 // [j][d]

using u64 = unsigned long long;

__device__ __forceinline__ u64 f2fma(u64 a, u64 b, u64 c) {
    u64 d; asm("fma.rn.f32x2 %0, %1, %2, %3;" : "=l"(d) : "l"(a), "l"(b), "l"(c)); return d;
}
__device__ __forceinline__ u64 packdup(float x) {
    u64 d; asm("mov.b64 %0, {%1, %2};" : "=l"(d) : "f"(x), "f"(x)); return d;
}
__device__ __forceinline__ float2 unpk(u64 v) {
    float2 r; asm("mov.b64 {%0, %1}, %2;" : "=f"(r.x), "=f"(r.y) : "l"(v)); return r;
}

// ---------------------------------------------------------------------------
// 4x4 transpose across lanes {l, l^8, l^16, l^24}.
// ---------------------------------------------------------------------------
__device__ __forceinline__ void xpose44(float& v0, float& v1, float& v2, float& v3, int lane) {
    bool bi = (lane & 16) != 0;
    bool ii = (lane & 8) != 0;
    float s0 = bi ? v0 : v2;
    float s1 = bi ? v1 : v3;
    float r0 = __shfl_xor_sync(0xffffffffu, s0, 16);
    float r1 = __shfl_xor_sync(0xffffffffu, s1, 16);
    v0 = bi ? r0 : v0;  v1 = bi ? r1 : v1;
    v2 = bi ? v2 : r0;  v3 = bi ? v3 : r1;
    float t0 = ii ? v0 : v1;
    float t1 = ii ? v2 : v3;
    float q0 = __shfl_xor_sync(0xffffffffu, t0, 8);
    float q1 = __shfl_xor_sync(0xffffffffu, t1, 8);
    v0 = ii ? q0 : v0;  v2 = ii ? q1 : v2;
    v1 = ii ? v1 : q0;  v3 = ii ? v3 : q1;
}

// Load 128 rows x KD cols (row-major) -> At[k][128], conflict-free STS.128.
template<int KD>
__device__ __forceinline__ void loadTileT(const float* __restrict__ src, long row0,
                                          float* At, int tid) {
    int w = tid >> 5, lane = tid & 31;
    int g = lane & 7, i = lane >> 3;
    int rband = w * 32 + g * 4;
    const float* rowp = src + (row0 + rband + i) * KD;
#pragma unroll
    for (int k0 = 0; k0 < KD; k0 += 4) {
        float4 v = *reinterpret_cast<const float4*>(rowp + k0);
        xpose44(v.x, v.y, v.z, v.w, lane);
        *reinterpret_cast<float4*>(At + (k0 + i) * 128 + rband) = v;
    }
}

__device__ __forceinline__ void copyF4(const float* __restrict__ src, float* dst, int n, int tid) {
    const float4* s = reinterpret_cast<const float4*>(src);
    float4* d = reinterpret_cast<float4*>(dst);
    for (int i = tid; i < n / 4; i += 128) d[i] = s[i];
}

// ---------------------------------------------------------------------------
// GEMM core: rows lane*4..+3, cols c0..c0+2*NBP-1 (f32x2 pairs over cols).
// ---------------------------------------------------------------------------
template<int KK, int NBP, int BSTR>
__device__ __forceinline__ void gemm2(const float* At, const float* Bt,
                                      int lane, int c0, u64 (&acc)[4][NBP]) {
#pragma unroll 8
    for (int k = 0; k < KK; ++k) {
        float4 a4 = *reinterpret_cast<const float4*>(At + k * 128 + lane * 4);
        u64 ad0 = packdup(a4.x), ad1 = packdup(a4.y), ad2 = packdup(a4.z), ad3 = packdup(a4.w);
        u64 bp[NBP];
#pragma unroll
        for (int ii = 0; ii < NBP / 2; ++ii) {
            ulonglong2 b = *reinterpret_cast<const ulonglong2*>(Bt + k * BSTR + c0 + 4 * ii);
            bp[2 * ii] = b.x; bp[2 * ii + 1] = b.y;
        }
#pragma unroll
        for (int j = 0; j < NBP; ++j) {
            acc[0][j] = f2fma(ad0, bp[j], acc[0][j]);
            acc[1][j] = f2fma(ad1, bp[j], acc[1][j]);
            acc[2][j] = f2fma(ad2, bp[j], acc[2][j]);
            acc[3][j] = f2fma(ad3, bp[j], acc[3][j]);
        }
    }
}

// transpose-store acc tile into At[col][128] (optional relu); conflict-free STS.128.
template<bool RELU>
__device__ __forceinline__ void storeT8(float* At, int lane, int c0, const u64 (&acc)[4][8]) {
#pragma unroll
    for (int j = 0; j < 8; ++j) {
        float2 p0 = unpk(acc[0][j]), p1 = unpk(acc[1][j]), p2 = unpk(acc[2][j]), p3 = unpk(acc[3][j]);
        float4 lo = make_float4(p0.x, p1.x, p2.x, p3.x);
        float4 hi = make_float4(p0.y, p1.y, p2.y, p3.y);
        if (RELU) {
            lo.x = fmaxf(lo.x, 0.f); lo.y = fmaxf(lo.y, 0.f); lo.z = fmaxf(lo.z, 0.f); lo.w = fmaxf(lo.w, 0.f);
            hi.x = fmaxf(hi.x, 0.f); hi.y = fmaxf(hi.y, 0.f); hi.z = fmaxf(hi.z, 0.f); hi.w = fmaxf(hi.w, 0.f);
        }
        *reinterpret_cast<float4*>(At + (c0 + 2 * j)     * 128 + lane * 4) = lo;
        *reinterpret_cast<float4*>(At + (c0 + 2 * j + 1) * 128 + lane * 4) = hi;
    }
}

__device__ __forceinline__ void initBias(const float* b, int c0, u64 (&acc)[4][8]) {
    ulonglong2 b01 = *reinterpret_cast<const ulonglong2*>(b + c0);
    ulonglong2 b23 = *reinterpret_cast<const ulonglong2*>(b + c0 + 4);
    ulonglong2 b45 = *reinterpret_cast<const ulonglong2*>(b + c0 + 8);
    ulonglong2 b67 = *reinterpret_cast<const ulonglong2*>(b + c0 + 12);
#pragma unroll
    for (int r = 0; r < 4; ++r) {
        acc[r][0] = b01.x; acc[r][1] = b01.y; acc[r][2] = b23.x; acc[r][3] = b23.y;
        acc[r][4] = b45.x; acc[r][5] = b45.y; acc[r][6] = b67.x; acc[r][7] = b67.y;
    }
}

__device__ __forceinline__ void storeRows16(float* dst, long rstride, long row0, int lane,
                                            int c0, const u64 (&acc)[4][8]) {
#pragma unroll
    for (int r = 0; r < 4; ++r) {
        float* p = dst + (row0 + lane * 4 + r) * rstride + c0;
        *reinterpret_cast<ulonglong2*>(p)      = make_ulonglong2(acc[r][0], acc[r][1]);
        *reinterpret_cast<ulonglong2*>(p + 4)  = make_ulonglong2(acc[r][2], acc[r][3]);
        *reinterpret_cast<ulonglong2*>(p + 8)  = make_ulonglong2(acc[r][4], acc[r][5]);
        *reinterpret_cast<ulonglong2*>(p + 12) = make_ulonglong2(acc[r][6], acc[r][7]);
    }
}

// ---------------------------------------------------------------------------
// Setup: transpose weights once; compute KW2T and Kb2.
// ---------------------------------------------------------------------------
__global__ void __launch_bounds__(256) kSetup(
    const float* __restrict__ ew1, const float* __restrict__ ew2, const float* __restrict__ eb2,
    const float* __restrict__ dw1, const float* __restrict__ dw2, const float* __restrict__ Kw) {
    int tid = threadIdx.x;
    for (int o = tid; o < 2048; o += 256) g_ew1T[o] = ew1[(o & 63) * 32 + (o >> 6)];
    for (int o = tid; o < 4096; o += 256) g_ew2T[o] = ew2[(o & 63) * 64 + (o >> 6)];
    for (int o = tid; o < 4096; o += 256) g_dw1T[o] = dw1[(o & 63) * 64 + (o >> 6)];
    for (int o = tid; o < 2048; o += 256) g_dw2T[o] = dw2[(o & 31) * 64 + (o >> 5)];
    for (int o = tid; o < 4096; o += 256) {
        int j = o >> 6, lp = o & 63;
        float s = 0.f;
#pragma unroll 8
        for (int l = 0; l < 64; ++l) s += ew2[l * 64 + j] * Kw[lp * 64 + l];
        g_KW2T[o] = s;
    }
    if (tid < 64) {
        float s = 0.f;
        for (int l = 0; l < 64; ++l) s += Kw[tid * 64 + l] * eb2[l];
        g_Kb2[tid] = s;
    }
}

// ---------------------------------------------------------------------------
// Koopman power table
// ---------------------------------------------------------------------------
__device__ __forceinline__ void mm64_step(const float* sA, float* sB, float* gout, int tid) {
    float r[16];
#pragma unroll
    for (int t = 0; t < 16; ++t) {
        int o = tid + t * 256, row = o >> 6, c = o & 63;
        float acc = 0.f;
#pragma unroll 8
        for (int k = 0; k < 64; ++k) acc += sA[row * 64 + k] * sB[k * 64 + c];
        r[t] = acc;
    }
    __syncthreads();
#pragma unroll
    for (int t = 0; t < 16; ++t) { int o = tid + t * 256; sB[o] = r[t]; gout[o] = r[t]; }
    __syncthreads();
}

__global__ void __launch_bounds__(256) kA1(const float* __restrict__ Kw) {
    __shared__ float sA[4096], sB[4096];
    int tid = threadIdx.x;
#pragma unroll
    for (int t = 0; t < 16; ++t) {
        int o = tid + t * 256;
        float v = Kw[o];
        sA[o] = v; sB[o] = v; g_Mpow[0][o] = v;
    }
    __syncthreads();
    for (int p = 2; p <= 8; ++p) mm64_step(sA, sB, g_Mpow[p - 1], tid);     // -> K^8
#pragma unroll
    for (int t = 0; t < 16; ++t) { int o = tid + t * 256; sA[o] = sB[o]; }
    __syncthreads();
    for (int q = 2; q <= 8; ++q) mm64_step(sA, sB, g_Mpow[8 * q - 1], tid); // -> K^64
#pragma unroll
    for (int t = 0; t < 16; ++t) { int o = tid + t * 256; sA[o] = sB[o]; }
    __syncthreads();
    mm64_step(sA, sB, g_Mpow[127], tid);  // K^128
    mm64_step(sA, sB, g_Mpow[191], tid);  // K^192
}

__device__ __forceinline__ void mm64_gg(const float* __restrict__ ga, const float* __restrict__ gb,
                                        float* __restrict__ gd, float* sA, float* sB, int tid) {
#pragma unroll
    for (int t = 0; t < 16; ++t) { int o = tid + t * 256; sA[o] = ga[o]; sB[o] = gb[o]; }
    __syncthreads();
#pragma unroll
    for (int t = 0; t < 16; ++t) {
        int o = tid + t * 256, row = o >> 6, c = o & 63;
        float acc = 0.f;
#pragma unroll 8
        for (int k = 0; k < 64; ++k) acc += sA[row * 64 + k] * sB[k * 64 + c];
        gd[o] = acc;
    }
}

__global__ void __launch_bounds__(256) kA2a() {
    int q = blockIdx.x / 7 + 1, r = blockIdx.x % 7 + 1;
    __shared__ float sA[4096], sB[4096];
    mm64_gg(g_Mpow[8 * q - 1], g_Mpow[r - 1], g_Mpow[8 * q + r - 1], sA, sB, threadIdx.x);
}

__global__ void __launch_bounds__(256) kA2b() {
    int t = blockIdx.x / 64 + 1, m = blockIdx.x % 64 + 1;
    if (m == 64 && t <= 2) return;
    __shared__ float sA[4096], sB[4096];
    mm64_gg(g_Mpow[64 * t - 1], g_Mpow[m - 1], g_Mpow[64 * t + m - 1], sA, sB, threadIdx.x);
}

__global__ void __launch_bounds__(256) kAT() {   // MpowT[p] = Mpow[p]^T
    __shared__ float s[4096];
    int p = blockIdx.x, tid = threadIdx.x;
    for (int o = tid; o < 4096; o += 256) s[o] = g_Mpow[p][o];
    __syncthreads();
    for (int o = tid; o < 4096; o += 256) g_MpowT[p][o] = s[(o & 63) * 64 + (o >> 6)];
}

// ---------------------------------------------------------------------------
// Encoder: x -> z, z_dyn.  z_dyn fused as h @ (K W2)^T + K b2.
// ---------------------------------------------------------------------------
__global__ void __launch_bounds__(128) kEnc(
    const float* __restrict__ x,
    const float* __restrict__ eb1, const float* __restrict__ eb2,
    float* __restrict__ out)
{
    __shared__ float At[64 * 128];
    __shared__ float Bt[64 * 64];
    int tid = threadIdx.x;
    int lane = tid & 31;
    int c0 = (tid >> 5) * 16;
    long row0 = (long)blockIdx.x * 128;

    loadTileT<32>(x, row0, At, tid);
    copyF4(g_ew1T, Bt, 2048, tid);
    __syncthreads();

    u64 acc[4][8];
    initBias(eb1, c0, acc);
    gemm2<32, 8, 64>(At, Bt, lane, c0, acc);
    __syncthreads();

    storeT8<true>(At, lane, c0, acc);
    copyF4(g_ew2T, Bt, 4096, tid);
    __syncthreads();

    initBias(eb2, c0, acc);
    gemm2<64, 8, 64>(At, Bt, lane, c0, acc);
    storeRows16(out + OFF_Z, Ln, row0, lane, c0, acc);
    __syncthreads();

    copyF4(g_KW2T, Bt, 4096, tid);
    __syncthreads();

    initBias(g_Kb2, c0, acc);
    gemm2<64, 8, 64>(At, Bt, lane, c0, acc);
    storeRows16(out + OFF_ZDYN, Ln, row0, lane, c0, acc);
}

// ---------------------------------------------------------------------------
// z_last transpose: g_zlastT[l][b] = z[b][S-1][l]
// ---------------------------------------------------------------------------
__global__ void __launch_bounds__(256) kT(const float* __restrict__ z) {
    int o = blockIdx.x * 256 + threadIdx.x;
    int b = o >> 6, l = o & 63;
    g_zlastT[l * Bn + b] = z[((long)b * Sn + (Sn - 1)) * Ln + l];
}

// ---------------------------------------------------------------------------
// Decoder for z and z_dyn segments only.  grid = 8192.
// ---------------------------------------------------------------------------
__global__ void __launch_bounds__(128) kDecZZ(
    float* __restrict__ out,
    const float* __restrict__ db1, const float* __restrict__ db2)
{
    __shared__ float At[64 * 128];
    __shared__ float Bt[64 * 64];
    int tid = threadIdx.x;
    int lane = tid & 31;
    int c0 = (tid >> 5) * 16;
    int bid = blockIdx.x;

    const float* zin;
    float* xout;
    long row0;
    if (bid < 4096) { zin = out + OFF_Z;    xout = out + OFF_XREC; row0 = (long)bid * 128; }
    else            { zin = out + OFF_ZDYN; xout = out + OFF_XDYN; row0 = (long)(bid - 4096) * 128; }

    loadTileT<64>(zin, row0, At, tid);
    copyF4(g_dw1T, Bt, 4096, tid);
    __syncthreads();

    u64 acc[4][8];
    initBias(db1, c0, acc);
    gemm2<64, 8, 64>(At, Bt, lane, c0, acc);
    __syncthreads();

    storeT8<true>(At, lane, c0, acc);
    copyF4(g_dw2T, Bt, 2048, tid);
    __syncthreads();

    int d0 = (tid >> 5) * 8;
    u64 acc2[4][4];
    {
        ulonglong2 b01 = *reinterpret_cast<const ulonglong2*>(db2 + d0);
        ulonglong2 b23 = *reinterpret_cast<const ulonglong2*>(db2 + d0 + 4);
#pragma unroll
        for (int r = 0; r < 4; ++r) { acc2[r][0] = b01.x; acc2[r][1] = b01.y; acc2[r][2] = b23.x; acc2[r][3] = b23.y; }
    }
    gemm2<64, 4, 32>(At, Bt, lane, d0, acc2);

#pragma unroll
    for (int r = 0; r < 4; ++r) {
        float* pdst = xout + (row0 + lane * 4 + r) * Dn + d0;
        *reinterpret_cast<ulonglong2*>(pdst)     = make_ulonglong2(acc2[r][0], acc2[r][1]);
        *reinterpret_cast<ulonglong2*>(pdst + 4) = make_ulonglong2(acc2[r][2], acc2[r][3]);
    }
}

// ---------------------------------------------------------------------------
// Fused pred rollout + decoder: per CTA (p, 128 b's):
//   zp = z_last @ (K^(p+1))^T  (in regs) -> At (transposed) -> MLP -> x_pred.
// grid = 256*8.  Eliminates the 256MB g_zpred roundtrip entirely.
// ---------------------------------------------------------------------------
__global__ void __launch_bounds__(128) kPredDec(
    float* __restrict__ out,
    const float* __restrict__ db1, const float* __restrict__ db2)
{
    __shared__ float At[64 * 128];
    __shared__ float Bt[64 * 64];
    int tid = threadIdx.x;
    int lane = tid & 31;
    int c0 = (tid >> 5) * 16;
    int p = blockIdx.x >> 3;
    int b0 = (blockIdx.x & 7) * 128;

    // At[k][128] <- g_zlastT[k][b0..b0+127]  (coalesced, no transpose needed)
    for (int u = tid; u < 64 * 32; u += 128) {
        int k = u >> 5, cq = (u & 31) * 4;
        *reinterpret_cast<float4*>(At + k * 128 + cq) =
            *reinterpret_cast<const float4*>(g_zlastT + k * Bn + b0 + cq);
    }
    copyF4(g_MpowT[p], Bt, 4096, tid);
    __syncthreads();

    // Phase 0: zp = z_last @ M^T
    u64 acc[4][8];
#pragma unroll
    for (int j = 0; j < 8; ++j)
#pragma unroll
        for (int r = 0; r < 4; ++r) acc[r][j] = 0ull;
    gemm2<64, 8, 64>(At, Bt, lane, c0, acc);
    __syncthreads();

    storeT8<false>(At, lane, c0, acc);          // zp -> At[l][128] (no relu)
    copyF4(g_dw1T, Bt, 4096, tid);
    __syncthreads();

    // Phase 1: h = relu(zp@W1^T + b1)
    initBias(db1, c0, acc);
    gemm2<64, 8, 64>(At, Bt, lane, c0, acc);
    __syncthreads();

    storeT8<true>(At, lane, c0, acc);
    copyF4(g_dw2T, Bt, 2048, tid);
    __syncthreads();

    // Phase 2: x_pred = h@W2^T + b2
    int d0 = (tid >> 5) * 8;
    u64 acc2[4][4];
    {
        ulonglong2 b01 = *reinterpret_cast<const ulonglong2*>(db2 + d0);
        ulonglong2 b23 = *reinterpret_cast<const ulonglong2*>(db2 + d0 + 4);
#pragma unroll
        for (int r = 0; r < 4; ++r) { acc2[r][0] = b01.x; acc2[r][1] = b01.y; acc2[r][2] = b23.x; acc2[r][3] = b23.y; }
    }
    gemm2<64, 4, 32>(At, Bt, lane, d0, acc2);

    // x_pred row for batch b, step p lives at (b*P + p)
#pragma unroll
    for (int r = 0; r < 4; ++r) {
        long b = b0 + lane * 4 + r;
        float* pdst = out + OFF_XPRED + (b * Pn + p) * Dn + d0;
        *reinterpret_cast<ulonglong2*>(pdst)     = make_ulonglong2(acc2[r][0], acc2[r][1]);
        *reinterpret_cast<ulonglong2*>(pdst + 4) = make_ulonglong2(acc2[r][2], acc2[r][3]);
    }
}

// ---------------------------------------------------------------------------
extern "C" void kernel_launch(void* const* d_in, const int* in_sizes, int n_in,
                              void* d_out, int out_size) {
    const float* x   = (const float*)d_in[0];
    const float* ew1 = (const float*)d_in[1];
    const float* eb1 = (const float*)d_in[2];
    const float* ew2 = (const float*)d_in[3];
    const float* eb2 = (const float*)d_in[4];
    const float* dw1 = (const float*)d_in[5];
    const float* db1 = (const float*)d_in[6];
    const float* dw2 = (const float*)d_in[7];
    const float* db2 = (const float*)d_in[8];
    const float* Kw  = (const float*)d_in[9];
    float* out = (float*)d_out;

    // Order chosen so the big decoder is the 4th launch (ncu captures it).
    kSetup<<<1, 256>>>(ew1, ew2, eb2, dw1, dw2, Kw);
    kEnc<<<BS / 128, 128>>>(x, eb1, eb2, out);
    kT<<<256, 256>>>(out + OFF_Z);
    kDecZZ<<<BS / 128 * 2, 128>>>(out, db1, db2);

    // Power table only needed by kPredDec — runs after the decoders.
    kA1<<<1, 256>>>(Kw);
    kA2a<<<49, 256>>>();
    kA2b<<<192, 256>>>();
    kAT<<<256, 256>>>();

    kPredDec<<<Pn * 8, 128>>>(out, db1, db2);
}

// round 13
// speedup vs baseline: 1.8543x; 1.8543x over previous
#include <cuda_runtime.h>

// DeepKoopman: B=1024,S=512,D=32,L=64,H=64,P=256
// Outputs: x_rec[B,S,D], x_dyn[B,S,D], x_pred[B,P,D], z[B,S,L], z_dyn[B,S,L]

namespace {
constexpr int Bn = 1024, Sn = 512, Dn = 32, Ln = 64, Pn = 256;
constexpr int BS = Bn * Sn;
constexpr long OFF_XREC  = 0;
constexpr long OFF_XDYN  = (long)BS * Dn;
constexpr long OFF_XPRED = OFF_XDYN * 2;
constexpr long OFF_Z     = OFF_XPRED + (long)Bn * Pn * Dn;
constexpr long OFF_ZDYN  = OFF_Z + (long)BS * Ln;
}

// scratch (device globals; no allocation allowed)
__device__ float g_Mpow[256][4096];               // K^p row-major
__device__ float g_MpowT[256][4096];              // transposed
__device__ float g_zpred[(long)Bn * Pn * Ln];     // [P,B,L]
__device__ float g_zlastT[Ln * Bn];               // [L,B]
__device__ float g_ew1T[32 * 64];                 // [i][j]
__device__ float g_ew2T[64 * 64];                 // [j][l]
__device__ float g_KW2T[64 * 64];                 // [j][l'] of (K@W2)
__device__ float g_Kb2[64];                       // K@b2
__device__ float g_dw1T[64 * 64];                 // [l][j]
__device__ float g_dw2T[64 * 32];                 // [j][d]

using u64 = unsigned long long;

__device__ __forceinline__ u64 f2fma(u64 a, u64 b, u64 c) {
    u64 d; asm("fma.rn.f32x2 %0, %1, %2, %3;" : "=l"(d) : "l"(a), "l"(b), "l"(c)); return d;
}
__device__ __forceinline__ u64 packdup(float x) {
    u64 d; asm("mov.b64 %0, {%1, %2};" : "=l"(d) : "f"(x), "f"(x)); return d;
}
__device__ __forceinline__ float2 unpk(u64 v) {
    float2 r; asm("mov.b64 {%0, %1}, %2;" : "=f"(r.x), "=f"(r.y) : "l"(v)); return r;
}

// ---------------------------------------------------------------------------
// Swizzled A-tile layout: At float-index(k,row) = k*128 + (chunk(row)^((k>>2)&15))*4 + (row&3)
// GEMM A-read (lane owns chunk=lane): float4 at k*128 + ((lane^c)<<2)  — conflict-free.
// Tile-load STS (lanes span fc=k>>2 at fixed rows): chunks (m^fc) — ≤2-way.
// ---------------------------------------------------------------------------
__device__ __forceinline__ float4 ldA(const float* At, int k, int lane) {
    return *reinterpret_cast<const float4*>(At + k * 128 + ((lane ^ ((k >> 2) & 15)) << 2));
}

template<int NBP, int BSTR>
__device__ __forceinline__ void loadB(const float* Bt, int k, int c0, u64* b) {
#pragma unroll
    for (int ii = 0; ii < NBP / 2; ++ii) {
        ulonglong2 t = *reinterpret_cast<const ulonglong2*>(Bt + k * BSTR + c0 + 4 * ii);
        b[2 * ii] = t.x; b[2 * ii + 1] = t.y;
    }
}

template<int NBP>
__device__ __forceinline__ void fmas(float4 a, const u64* b, u64 (&acc)[4][NBP]) {
    u64 ad0 = packdup(a.x), ad1 = packdup(a.y), ad2 = packdup(a.z), ad3 = packdup(a.w);
#pragma unroll
    for (int j = 0; j < NBP; ++j) {
        acc[0][j] = f2fma(ad0, b[j], acc[0][j]);
        acc[1][j] = f2fma(ad1, b[j], acc[1][j]);
        acc[2][j] = f2fma(ad2, b[j], acc[2][j]);
        acc[3][j] = f2fma(ad3, b[j], acc[3][j]);
    }
}

// Software-pipelined GEMM: prefetch k+1 A/B during k's fma burst.
template<int KK, int NBP, int BSTR>
__device__ __forceinline__ void gemm2(const float* At, const float* Bt,
                                      int lane, int c0, u64 (&acc)[4][NBP]) {
    float4 a = ldA(At, 0, lane);
    u64 b[NBP];
    loadB<NBP, BSTR>(Bt, 0, c0, b);
#pragma unroll 8
    for (int k = 0; k < KK - 1; ++k) {
        float4 an = ldA(At, k + 1, lane);
        u64 bn[NBP];
        loadB<NBP, BSTR>(Bt, k + 1, c0, bn);
        fmas<NBP>(a, b, acc);
        a = an;
#pragma unroll
        for (int j = 0; j < NBP; ++j) b[j] = bn[j];
    }
    fmas<NBP>(a, b, acc);
}

// Coalesced + swizzled tile load: 128 rows x KD cols row-major -> swizzled At.
template<int KD>
__device__ __forceinline__ void loadTileSwz(const float* __restrict__ src, long row0,
                                            float* At, int tid) {
    constexpr int F4 = KD / 4;
#pragma unroll
    for (int it = 0; it < F4; ++it) {
        int g = tid + it * 128;
        int row = g / F4, fc = g % F4;
        float4 v = *reinterpret_cast<const float4*>(src + (row0 + row) * KD + fc * 4);
        float vv[4] = {v.x, v.y, v.z, v.w};
        int base = ((((row >> 2) ^ fc) & 31) << 2) | (row & 3);
#pragma unroll
        for (int i = 0; i < 4; ++i)
            At[(fc * 4 + i) * 128 + base] = vv[i];
    }
}

// transpose-store acc (optional relu) into swizzled At; conflict-free STS.128.
template<bool RELU>
__device__ __forceinline__ void storeT8(float* At, int lane, int c0, const u64 (&acc)[4][8]) {
#pragma unroll
    for (int j = 0; j < 8; ++j) {
        float2 p0 = unpk(acc[0][j]), p1 = unpk(acc[1][j]), p2 = unpk(acc[2][j]), p3 = unpk(acc[3][j]);
        float4 lo = make_float4(p0.x, p1.x, p2.x, p3.x);
        float4 hi = make_float4(p0.y, p1.y, p2.y, p3.y);
        if (RELU) {
            lo.x = fmaxf(lo.x, 0.f); lo.y = fmaxf(lo.y, 0.f); lo.z = fmaxf(lo.z, 0.f); lo.w = fmaxf(lo.w, 0.f);
            hi.x = fmaxf(hi.x, 0.f); hi.y = fmaxf(hi.y, 0.f); hi.z = fmaxf(hi.z, 0.f); hi.w = fmaxf(hi.w, 0.f);
        }
        int k0 = c0 + 2 * j, k1 = k0 + 1;
        *reinterpret_cast<float4*>(At + k0 * 128 + ((lane ^ ((k0 >> 2) & 15)) << 2)) = lo;
        *reinterpret_cast<float4*>(At + k1 * 128 + ((lane ^ ((k1 >> 2) & 15)) << 2)) = hi;
    }
}

__device__ __forceinline__ void copyF4(const float* __restrict__ src, float* dst, int n, int tid) {
    const float4* s = reinterpret_cast<const float4*>(src);
    float4* d = reinterpret_cast<float4*>(dst);
    for (int i = tid; i < n / 4; i += 128) d[i] = s[i];
}

__device__ __forceinline__ void initBias(const float* b, int c0, u64 (&acc)[4][8]) {
    ulonglong2 b01 = *reinterpret_cast<const ulonglong2*>(b + c0);
    ulonglong2 b23 = *reinterpret_cast<const ulonglong2*>(b + c0 + 4);
    ulonglong2 b45 = *reinterpret_cast<const ulonglong2*>(b + c0 + 8);
    ulonglong2 b67 = *reinterpret_cast<const ulonglong2*>(b + c0 + 12);
#pragma unroll
    for (int r = 0; r < 4; ++r) {
        acc[r][0] = b01.x; acc[r][1] = b01.y; acc[r][2] = b23.x; acc[r][3] = b23.y;
        acc[r][4] = b45.x; acc[r][5] = b45.y; acc[r][6] = b67.x; acc[r][7] = b67.y;
    }
}

__device__ __forceinline__ void storeRows16(float* dst, long rstride, long row0, int lane,
                                            int c0, const u64 (&acc)[4][8]) {
#pragma unroll
    for (int r = 0; r < 4; ++r) {
        float* p = dst + (row0 + lane * 4 + r) * rstride + c0;
        *reinterpret_cast<ulonglong2*>(p)      = make_ulonglong2(acc[r][0], acc[r][1]);
        *reinterpret_cast<ulonglong2*>(p + 4)  = make_ulonglong2(acc[r][2], acc[r][3]);
        *reinterpret_cast<ulonglong2*>(p + 8)  = make_ulonglong2(acc[r][4], acc[r][5]);
        *reinterpret_cast<ulonglong2*>(p + 12) = make_ulonglong2(acc[r][6], acc[r][7]);
    }
}

// ---------------------------------------------------------------------------
// Setup: transpose weights once; compute KW2T and Kb2.
// ---------------------------------------------------------------------------
__global__ void __launch_bounds__(256) kSetup(
    const float* __restrict__ ew1, const float* __restrict__ ew2, const float* __restrict__ eb2,
    const float* __restrict__ dw1, const float* __restrict__ dw2, const float* __restrict__ Kw) {
    int tid = threadIdx.x;
    for (int o = tid; o < 2048; o += 256) g_ew1T[o] = ew1[(o & 63) * 32 + (o >> 6)];
    for (int o = tid; o < 4096; o += 256) g_ew2T[o] = ew2[(o & 63) * 64 + (o >> 6)];
    for (int o = tid; o < 4096; o += 256) g_dw1T[o] = dw1[(o & 63) * 64 + (o >> 6)];
    for (int o = tid; o < 2048; o += 256) g_dw2T[o] = dw2[(o & 31) * 64 + (o >> 5)];
    for (int o = tid; o < 4096; o += 256) {
        int j = o >> 6, lp = o & 63;
        float s = 0.f;
#pragma unroll 8
        for (int l = 0; l < 64; ++l) s += ew2[l * 64 + j] * Kw[lp * 64 + l];
        g_KW2T[o] = s;
    }
    if (tid < 64) {
        float s = 0.f;
        for (int l = 0; l < 64; ++l) s += Kw[tid * 64 + l] * eb2[l];
        g_Kb2[tid] = s;
    }
}

// ---------------------------------------------------------------------------
// Koopman power table — register-blocked f32x2 64x64 matmul core.
// sA padded to stride 68; thread (tr,tc) owns rows 4tr..+3, cols 4tc..+3.
// ---------------------------------------------------------------------------
__device__ __forceinline__ void mm64core(const float* sA, const float* sB,
                                         u64 (&acc)[4][2], int tr, int tc) {
#pragma unroll 8
    for (int k = 0; k < 64; ++k) {
        ulonglong2 b = *reinterpret_cast<const ulonglong2*>(sB + k * 64 + tc * 4);
#pragma unroll
        for (int r = 0; r < 4; ++r) {
            u64 ad = packdup(sA[(tr * 4 + r) * 68 + k]);
            acc[r][0] = f2fma(ad, b.x, acc[r][0]);
            acc[r][1] = f2fma(ad, b.y, acc[r][1]);
        }
    }
}

__device__ __forceinline__ void mm64_wb(float* dst64, const u64 (&acc)[4][2], int tr, int tc) {
#pragma unroll
    for (int r = 0; r < 4; ++r) {
        float2 p0 = unpk(acc[r][0]), p1 = unpk(acc[r][1]);
        *reinterpret_cast<float4*>(dst64 + (tr * 4 + r) * 64 + tc * 4) =
            make_float4(p0.x, p0.y, p1.x, p1.y);
    }
}

// one chain step: sB <- sA * sB; also writes result to gout.
__device__ __forceinline__ void mm64_step(const float* sA, float* sB, float* gout, int tid) {
    int tr = tid >> 4, tc = tid & 15;
    u64 acc[4][2] = {};
    mm64core(sA, sB, acc, tr, tc);
    __syncthreads();
    mm64_wb(sB, acc, tr, tc);
    mm64_wb(gout, acc, tr, tc);
    __syncthreads();
}

__global__ void __launch_bounds__(256) kA1(const float* __restrict__ Kw) {
    __shared__ float sA[64 * 68], sB[4096];
    int tid = threadIdx.x;
    for (int o = tid; o < 4096; o += 256) {
        float v = Kw[o];
        sA[(o >> 6) * 68 + (o & 63)] = v;
        sB[o] = v;
        g_Mpow[0][o] = v;
    }
    __syncthreads();
    for (int p = 2; p <= 8; ++p) mm64_step(sA, sB, g_Mpow[p - 1], tid);     // -> K^8
    for (int o = tid; o < 4096; o += 256) sA[(o >> 6) * 68 + (o & 63)] = sB[o];
    __syncthreads();
    for (int q = 2; q <= 8; ++q) mm64_step(sA, sB, g_Mpow[8 * q - 1], tid); // -> K^64
    for (int o = tid; o < 4096; o += 256) sA[(o >> 6) * 68 + (o & 63)] = sB[o];
    __syncthreads();
    mm64_step(sA, sB, g_Mpow[127], tid);  // K^128
    mm64_step(sA, sB, g_Mpow[191], tid);  // K^192
}

__device__ __forceinline__ void mm64_gg(const float* __restrict__ ga, const float* __restrict__ gb,
                                        float* __restrict__ gd, float* sA, float* sB, int tid) {
    for (int o = tid; o < 4096; o += 256) {
        sA[(o >> 6) * 68 + (o & 63)] = ga[o];
        sB[o] = gb[o];
    }
    __syncthreads();
    int tr = tid >> 4, tc = tid & 15;
    u64 acc[4][2] = {};
    mm64core(sA, sB, acc, tr, tc);
    mm64_wb(gd, acc, tr, tc);
}

__global__ void __launch_bounds__(256) kA2a() {
    int q = blockIdx.x / 7 + 1, r = blockIdx.x % 7 + 1;
    __shared__ float sA[64 * 68], sB[4096];
    mm64_gg(g_Mpow[8 * q - 1], g_Mpow[r - 1], g_Mpow[8 * q + r - 1], sA, sB, threadIdx.x);
}

__global__ void __launch_bounds__(256) kA2b() {
    int t = blockIdx.x / 64 + 1, m = blockIdx.x % 64 + 1;
    if (m == 64 && t <= 2) return;
    __shared__ float sA[64 * 68], sB[4096];
    mm64_gg(g_Mpow[64 * t - 1], g_Mpow[m - 1], g_Mpow[64 * t + m - 1], sA, sB, threadIdx.x);
}

__global__ void __launch_bounds__(256) kAT() {   // MpowT[p] = Mpow[p]^T
    __shared__ float s[4096];
    int p = blockIdx.x, tid = threadIdx.x;
    for (int o = tid; o < 4096; o += 256) s[o] = g_Mpow[p][o];
    __syncthreads();
    for (int o = tid; o < 4096; o += 256) g_MpowT[p][o] = s[(o & 63) * 64 + (o >> 6)];
}

// ---------------------------------------------------------------------------
// Encoder: x -> z, z_dyn.  z_dyn fused as h @ (K W2)^T + K b2.
// ---------------------------------------------------------------------------
__global__ void __launch_bounds__(128) kEnc(
    const float* __restrict__ x,
    const float* __restrict__ eb1, const float* __restrict__ eb2,
    float* __restrict__ out)
{
    __shared__ __align__(16) float At[64 * 128];
    __shared__ __align__(16) float Bt[64 * 64];
    int tid = threadIdx.x;
    int lane = tid & 31;
    int c0 = (tid >> 5) * 16;
    long row0 = (long)blockIdx.x * 128;

    loadTileSwz<32>(x, row0, At, tid);
    copyF4(g_ew1T, Bt, 2048, tid);
    __syncthreads();

    u64 acc[4][8];
    initBias(eb1, c0, acc);
    gemm2<32, 8, 64>(At, Bt, lane, c0, acc);
    __syncthreads();

    storeT8<true>(At, lane, c0, acc);
    copyF4(g_ew2T, Bt, 4096, tid);
    __syncthreads();

    initBias(eb2, c0, acc);
    gemm2<64, 8, 64>(At, Bt, lane, c0, acc);
    storeRows16(out + OFF_Z, Ln, row0, lane, c0, acc);
    __syncthreads();

    copyF4(g_KW2T, Bt, 4096, tid);
    __syncthreads();

    initBias(g_Kb2, c0, acc);
    gemm2<64, 8, 64>(At, Bt, lane, c0, acc);
    storeRows16(out + OFF_ZDYN, Ln, row0, lane, c0, acc);
}

// ---------------------------------------------------------------------------
// z_last transpose: g_zlastT[l][b] = z[b][S-1][l]
// ---------------------------------------------------------------------------
__global__ void __launch_bounds__(256) kT(const float* __restrict__ z) {
    int o = blockIdx.x * 256 + threadIdx.x;
    int b = o >> 6, l = o & 63;
    g_zlastT[l * Bn + b] = z[((long)b * Sn + (Sn - 1)) * Ln + l];
}

// ---------------------------------------------------------------------------
// Pred rollout: g_zpred[p][b] = z_last[b] @ (K^(p+1))^T.  grid = 256*8.
// ---------------------------------------------------------------------------
__global__ void __launch_bounds__(128) kPredZ() {
    __shared__ __align__(16) float At[64 * 128];
    __shared__ __align__(16) float Bt[64 * 64];
    int tid = threadIdx.x;
    int lane = tid & 31;
    int c0 = (tid >> 5) * 16;
    int p = blockIdx.x >> 3;
    int b0 = (blockIdx.x & 7) * 128;

    // At[k][b-chunks] swizzled <- g_zlastT[k][b0..b0+127] (coalesced, conflict-free)
    for (int u = tid; u < 64 * 32; u += 128) {
        int k = u >> 5, cb = u & 31;
        float4 t = *reinterpret_cast<const float4*>(g_zlastT + k * Bn + b0 + cb * 4);
        *reinterpret_cast<float4*>(At + k * 128 + ((cb ^ ((k >> 2) & 15)) << 2)) = t;
    }
    copyF4(g_MpowT[p], Bt, 4096, tid);
    __syncthreads();

    u64 acc[4][8];
#pragma unroll
    for (int j = 0; j < 8; ++j)
#pragma unroll
        for (int r = 0; r < 4; ++r) acc[r][j] = 0ull;
    gemm2<64, 8, 64>(At, Bt, lane, c0, acc);
    storeRows16(g_zpred, Ln, (long)p * Bn + b0, lane, c0, acc);
}

// ---------------------------------------------------------------------------
// Combined decoder: 3 segments (z->x_rec, z_dyn->x_dyn, z_pred->x_pred).
// ---------------------------------------------------------------------------
__global__ void __launch_bounds__(128) kDecAll(
    float* __restrict__ out,
    const float* __restrict__ db1, const float* __restrict__ db2)
{
    __shared__ __align__(16) float At[64 * 128];
    __shared__ __align__(16) float Bt[64 * 64];
    int tid = threadIdx.x;
    int lane = tid & 31;
    int c0 = (tid >> 5) * 16;
    int bid = blockIdx.x;

    const float* zin;
    float* xout;
    long row0;
    int is_pred = 0;
    if (bid < 4096)      { zin = out + OFF_Z;    xout = out + OFF_XREC;  row0 = (long)bid * 128; }
    else if (bid < 8192) { zin = out + OFF_ZDYN; xout = out + OFF_XDYN;  row0 = (long)(bid - 4096) * 128; }
    else                 { zin = g_zpred;        xout = out + OFF_XPRED; row0 = (long)(bid - 8192) * 128; is_pred = 1; }

    loadTileSwz<64>(zin, row0, At, tid);
    copyF4(g_dw1T, Bt, 4096, tid);
    __syncthreads();

    u64 acc[4][8];
    initBias(db1, c0, acc);
    gemm2<64, 8, 64>(At, Bt, lane, c0, acc);
    __syncthreads();

    storeT8<true>(At, lane, c0, acc);
    copyF4(g_dw2T, Bt, 2048, tid);
    __syncthreads();

    int d0 = (tid >> 5) * 8;
    u64 acc2[4][4];
    {
        ulonglong2 b01 = *reinterpret_cast<const ulonglong2*>(db2 + d0);
        ulonglong2 b23 = *reinterpret_cast<const ulonglong2*>(db2 + d0 + 4);
#pragma unroll
        for (int r = 0; r < 4; ++r) { acc2[r][0] = b01.x; acc2[r][1] = b01.y; acc2[r][2] = b23.x; acc2[r][3] = b23.y; }
    }
    gemm2<64, 4, 32>(At, Bt, lane, d0, acc2);

#pragma unroll
    for (int r = 0; r < 4; ++r) {
        long grow = row0 + lane * 4 + r;
        long orow = grow;
        if (is_pred) orow = ((grow & 1023) << 8) | (grow >> 10);  // [p][b] -> b*P+p
        float* pdst = xout + orow * Dn + d0;
        *reinterpret_cast<ulonglong2*>(pdst)     = make_ulonglong2(acc2[r][0], acc2[r][1]);
        *reinterpret_cast<ulonglong2*>(pdst + 4) = make_ulonglong2(acc2[r][2], acc2[r][3]);
    }
}

// ---------------------------------------------------------------------------
extern "C" void kernel_launch(void* const* d_in, const int* in_sizes, int n_in,
                              void* d_out, int out_size) {
    const float* x   = (const float*)d_in[0];
    const float* ew1 = (const float*)d_in[1];
    const float* eb1 = (const float*)d_in[2];
    const float* ew2 = (const float*)d_in[3];
    const float* eb2 = (const float*)d_in[4];
    const float* dw1 = (const float*)d_in[5];
    const float* db1 = (const float*)d_in[6];
    const float* dw2 = (const float*)d_in[7];
    const float* db2 = (const float*)d_in[8];
    const float* Kw  = (const float*)d_in[9];
    float* out = (float*)d_out;

    // Order: kEnc is the 6th launch so ncu (-s 5 -c 1) finally profiles it.
    kSetup<<<1, 256>>>(ew1, ew2, eb2, dw1, dw2, Kw);
    kA1<<<1, 256>>>(Kw);
    kA2a<<<49, 256>>>();
    kA2b<<<192, 256>>>();
    kAT<<<256, 256>>>();
    kEnc<<<BS / 128, 128>>>(x, eb1, eb2, out);

    kT<<<256, 256>>>(out + OFF_Z);
    kPredZ<<<Pn * 8, 128>>>();

    kDecAll<<<BS / 128 * 2 + (Bn * Pn) / 128, 128>>>(out, db1, db2);
}